// round 15
// baseline (speedup 1.0000x reference)
#include <cuda_runtime.h>
#include <cuda_bf16.h>

// Renderer: B=2, N=2048 points, S=128 image, K=16 per pixel, alpha composite.
//
// PER-PIXEL scatter binning + register-resident streaming top-16 + 4-wide
// batched candidate loads + WARP-INTERLEAVED pixel assignment:
//   K1 (project+bin): project each point to NDC; push (x, y, z, idx) into the
//       candidate list of every pixel whose center is within RADIUS per-axis
//       (<= 3x3 pixels per point). Lists stored TRANSPOSED (list[slot][pixel])
//       so render loads coalesce.
//   K2 (render): one thread per pixel. Warp w of block b handles pixel-warp
//       (b + gridDim.x * w): warps stay spatially coherent (32 contiguous
//       pixels) but each block's warps spread across the image, so dense
//       central warps distribute evenly over SMs (no straggler block).
//       Candidate loop is 4-wide load-batched (MLP=4); hits maintain a
//       16-slot register array sorted ascending by packed key
//       (z_bits<<32 | idx) via a fully-unrolled bubble insert (no local
//       memory). Composite is the plain front-to-back recurrence over the
//       already-sorted slots. Each thread re-zeroes its own counter
//       (device state returns to zero every call -> graph-replay safe).
// Packed keys preserve (z, index) lexicographic order -> deterministic under
// atomic push order and matches top_k's index-stable tie-breaking.

#define S_IMG    128
#define NPTS     2048
#define KHITS    16
#define RADIUS   0.02f
#define RAD2     (RADIUS * RADIUS)
#define INV_RAD2 (1.0f / RAD2)
#define ZNEAR    1.0f
#define FOCAL    1.7320508075688772f   // 1 / tan(30 deg)
#define B_MAX    2
#define NPIX     (B_MAX * S_IMG * S_IMG)   // 32768
#define CAP      40                    // peak mean ~11 candidates/pixel
#define KEY_MAX  0xffffffffffffffffULL

__device__ int    g_cnt [NPIX];             // zero at steady state
__device__ float4 g_list[CAP * NPIX];       // transposed: [slot][pixel] ~21MB

// ------------------------------------------------------------ project+bin --
__global__ __launch_bounds__(256) void project_bin_kernel(
    const float* __restrict__ points,   // [B, N, 3]
    const float* __restrict__ eye)      // [B, 3]
{
    const int g = blockIdx.x * blockDim.x + threadIdx.x;
    const int b = g / NPTS;
    const int i = g - b * NPTS;

    const float ex = eye[b * 3 + 0];
    const float ey = eye[b * 3 + 1];
    const float ez = eye[b * 3 + 2];

    // camera basis (look-at origin, up = +y)
    float zn  = rsqrtf(ex * ex + ey * ey + ez * ez);
    float zax = -ex * zn, zay = -ey * zn, zaz = -ez * zn;
    float xax = zaz, xaz = -zax;                 // up x z (x.y == 0)
    float xn  = rsqrtf(xax * xax + xaz * xaz);
    xax *= xn; xaz *= xn;
    float yax = zay * xaz;
    float yay = zaz * xax - zax * xaz;
    float yaz = -zay * xax;

    const float* p = points + (size_t)g * 3;
    float dx = p[0] - ex, dy = p[1] - ey, dz = p[2] - ez;
    float cz = dx * zax + dy * zay + dz * zaz;
    if (cz <= ZNEAR) return;

    float cx = dx * xax + dz * xaz;
    float cy = dx * yax + dy * yay + dz * yaz;
    float s  = FOCAL / cz;
    float x  = cx * s;
    float y  = cy * s;

    // pixels whose center satisfies |pxc - x| < R per axis.
    // pxc = 1-(2c+1)/S  =>  c in ((1-x-R)*S/2-0.5 , (1-x+R)*S/2-0.5).
    // Epsilon-widened; exact d2 test in K2 makes over-inclusion harmless.
    float c_lo = (1.0f - x - RADIUS) * (S_IMG * 0.5f) - 0.5f;
    float c_hi = (1.0f - x + RADIUS) * (S_IMG * 0.5f) - 0.5f;
    float r_lo = (1.0f - y - RADIUS) * (S_IMG * 0.5f) - 0.5f;
    float r_hi = (1.0f - y + RADIUS) * (S_IMG * 0.5f) - 0.5f;

    int cmin = max(0,         (int)ceilf (c_lo - 1e-4f));
    int cmax = min(S_IMG - 1, (int)floorf(c_hi + 1e-4f));
    int rmin = max(0,         (int)ceilf (r_lo - 1e-4f));
    int rmax = min(S_IMG - 1, (int)floorf(r_hi + 1e-4f));
    if (cmin > cmax || rmin > rmax) return;

    float4 e = make_float4(x, y, cz, __int_as_float(i));
    for (int rr = rmin; rr <= rmax; rr++) {
        for (int cc = cmin; cc <= cmax; cc++) {
            int pix = (b * S_IMG + rr) * S_IMG + cc;
            int slot = atomicAdd(&g_cnt[pix], 1);
            if (slot < CAP) g_list[slot * NPIX + pix] = e;
        }
    }
}

// -------- distance test + register bubble-insert (fully unrolled) ----------
__device__ __forceinline__ void try_insert(
    float4 q, float pxc, float pyc,
    unsigned long long* hk, float* hd)
{
    float ddx = pxc - q.x;
    float ddy = pyc - q.y;
    float d2  = fmaf(ddx, ddx, ddy * ddy);
    if (d2 < RAD2) {
        unsigned long long nk =
            ((unsigned long long)__float_as_uint(q.z) << 32)
            | (unsigned int)__float_as_int(q.w);
        float nd = d2;
        #pragma unroll
        for (int k = 0; k < KHITS; k++) {
            bool sw = nk < hk[k];
            unsigned long long tk = hk[k];
            float td = hd[k];
            hk[k] = sw ? nk : tk;  hd[k] = sw ? nd : td;
            nk    = sw ? tk : nk;  nd    = sw ? td : nd;
        }
    }
}

// ----------------------------------------------------------------- render --
__global__ __launch_bounds__(256) void render_px_kernel(
    const float* __restrict__ colors,   // [B, N, 3]
    float* __restrict__ out)            // [B, S, S, 3]
{
    // warp-interleaved pixel assignment: warp w of block b -> pixel-warp
    // (b + gridDim.x * w). Warps stay contiguous (coherent lanes); blocks
    // sample the image evenly -> balanced density per SM.
    const int lane = threadIdx.x & 31;
    const int wid  = threadIdx.x >> 5;
    const int pixwarp = blockIdx.x + gridDim.x * wid;
    const int pix  = pixwarp * 32 + lane;                   // 0 .. B*S*S-1
    const int b    = pix >> 14;                             // / (S*S)
    const int cnt  = min(g_cnt[pix], CAP);
    g_cnt[pix] = 0;                     // restore zero state for next call

    const float inv = 1.0f / (float)S_IMG;
    const int col = pix & (S_IMG - 1);
    const int row = (pix >> 7) & (S_IMG - 1);
    const float pxc = 1.0f - (2.0f * col + 1.0f) * inv;
    const float pyc = 1.0f - (2.0f * row + 1.0f) * inv;

    // register-resident sorted top-16 (ascending by key)
    // invalid slot: key = KEY_MAX, d2 = RAD2 (alpha == 0)
    unsigned long long hk[KHITS];
    float hd[KHITS];
    #pragma unroll
    for (int k = 0; k < KHITS; k++) { hk[k] = KEY_MAX; hd[k] = RAD2; }

    // ---- candidate loop: 4-wide batched loads (MLP = 4) ----
    int j = 0;
    for (; j + 4 <= cnt; j += 4) {
        float4 q0 = __ldg(&g_list[(j + 0) * NPIX + pix]);
        float4 q1 = __ldg(&g_list[(j + 1) * NPIX + pix]);
        float4 q2 = __ldg(&g_list[(j + 2) * NPIX + pix]);
        float4 q3 = __ldg(&g_list[(j + 3) * NPIX + pix]);
        try_insert(q0, pxc, pyc, hk, hd);
        try_insert(q1, pxc, pyc, hk, hd);
        try_insert(q2, pxc, pyc, hk, hd);
        try_insert(q3, pxc, pyc, hk, hd);
    }
    for (; j < cnt; j++) {
        float4 q = __ldg(&g_list[j * NPIX + pix]);
        try_insert(q, pxc, pyc, hk, hd);
    }

    // ---- front-to-back composite over already-sorted slots ----
    float T = 1.0f, r = 0.0f, g = 0.0f, bl = 0.0f;
    #pragma unroll
    for (int k = 0; k < KHITS; k++) {
        float a = 1.0f - hd[k] * INV_RAD2;     // == 0 for invalid slots
        a = fminf(fmaxf(a, 0.0f), 1.0f);
        float w = a * T;
        if (hk[k] != KEY_MAX) {
            const float* c = colors +
                (size_t)(b * NPTS +
                         (int)(unsigned int)(hk[k] & 0xffffffffu)) * 3;
            r  += w * __ldg(&c[0]);
            g  += w * __ldg(&c[1]);
            bl += w * __ldg(&c[2]);
        }
        T *= (1.0f - a);
    }

    float* o = out + (size_t)pix * 3;
    o[0] = r; o[1] = g; o[2] = bl;
}

// ----------------------------------------------------------------- launch ---
extern "C" void kernel_launch(void* const* d_in, const int* in_sizes, int n_in,
                              void* d_out, int out_size) {
    const float* points = (const float*)d_in[0];
    const float* eye    = (const float*)d_in[1];
    const float* colors = (const float*)d_in[2];
    float* out          = (float*)d_out;

    const int B = in_sizes[1] / 3;     // eye is [B,3]

    project_bin_kernel<<<(B * NPTS) / 256, 256>>>(points, eye);
    render_px_kernel<<<(B * S_IMG * S_IMG) / 256, 256>>>(colors, out);
}

// round 16
// speedup vs baseline: 1.0698x; 1.0698x over previous
#include <cuda_runtime.h>
#include <cuda_bf16.h>

// Renderer: B=2, N=2048 points, S=128 image, K=16 per pixel, alpha composite.
//
// PER-PIXEL scatter binning + register-resident streaming top-16 + 4-wide
// batched candidate loads + PDL (programmatic dependent launch) overlap:
//   K1 (project+bin): project each point to NDC; push (x, y, z, idx) into the
//       candidate list of every pixel whose center is within RADIUS per-axis
//       (<= 3x3 pixels per point). Lists stored TRANSPOSED (list[slot][pixel])
//       so render loads coalesce.
//   K2 (render): launched with programmaticStreamSerializationAllowed=1 so
//       its launch latency + preamble overlap K1. It computes pixel coords
//       and initializes its 16 register slots, then calls
//       cudaGridDependencySynchronize() (K1 never triggers early, so this
//       returns at K1 full completion -> all binning writes visible), then
//       reads its candidate list with 4-wide batched loads (MLP=4) and
//       maintains a sorted register top-16 by packed key (z_bits<<32 | idx)
//       via fully-unrolled bubble insert (no local memory). Composite is the
//       plain front-to-back recurrence over sorted slots. Each thread
//       re-zeroes its own counter (device state returns to zero every call
//       -> graph-replay deterministic).
// Packed keys preserve (z, index) lexicographic order -> deterministic under
// atomic push order and matches top_k's index-stable tie-breaking.

#define S_IMG    128
#define NPTS     2048
#define KHITS    16
#define RADIUS   0.02f
#define RAD2     (RADIUS * RADIUS)
#define INV_RAD2 (1.0f / RAD2)
#define ZNEAR    1.0f
#define FOCAL    1.7320508075688772f   // 1 / tan(30 deg)
#define B_MAX    2
#define NPIX     (B_MAX * S_IMG * S_IMG)   // 32768
#define CAP      40                    // peak mean ~11 candidates/pixel
#define KEY_MAX  0xffffffffffffffffULL

__device__ int    g_cnt [NPIX];             // zero at steady state
__device__ float4 g_list[CAP * NPIX];       // transposed: [slot][pixel] ~21MB

// ------------------------------------------------------------ project+bin --
__global__ __launch_bounds__(256) void project_bin_kernel(
    const float* __restrict__ points,   // [B, N, 3]
    const float* __restrict__ eye)      // [B, 3]
{
    const int g = blockIdx.x * blockDim.x + threadIdx.x;
    const int b = g / NPTS;
    const int i = g - b * NPTS;

    const float ex = eye[b * 3 + 0];
    const float ey = eye[b * 3 + 1];
    const float ez = eye[b * 3 + 2];

    // camera basis (look-at origin, up = +y)
    float zn  = rsqrtf(ex * ex + ey * ey + ez * ez);
    float zax = -ex * zn, zay = -ey * zn, zaz = -ez * zn;
    float xax = zaz, xaz = -zax;                 // up x z (x.y == 0)
    float xn  = rsqrtf(xax * xax + xaz * xaz);
    xax *= xn; xaz *= xn;
    float yax = zay * xaz;
    float yay = zaz * xax - zax * xaz;
    float yaz = -zay * xax;

    const float* p = points + (size_t)g * 3;
    float dx = p[0] - ex, dy = p[1] - ey, dz = p[2] - ez;
    float cz = dx * zax + dy * zay + dz * zaz;
    if (cz <= ZNEAR) return;

    float cx = dx * xax + dz * xaz;
    float cy = dx * yax + dy * yay + dz * yaz;
    float s  = FOCAL / cz;
    float x  = cx * s;
    float y  = cy * s;

    // pixels whose center satisfies |pxc - x| < R per axis.
    // pxc = 1-(2c+1)/S  =>  c in ((1-x-R)*S/2-0.5 , (1-x+R)*S/2-0.5).
    // Epsilon-widened; exact d2 test in K2 makes over-inclusion harmless.
    float c_lo = (1.0f - x - RADIUS) * (S_IMG * 0.5f) - 0.5f;
    float c_hi = (1.0f - x + RADIUS) * (S_IMG * 0.5f) - 0.5f;
    float r_lo = (1.0f - y - RADIUS) * (S_IMG * 0.5f) - 0.5f;
    float r_hi = (1.0f - y + RADIUS) * (S_IMG * 0.5f) - 0.5f;

    int cmin = max(0,         (int)ceilf (c_lo - 1e-4f));
    int cmax = min(S_IMG - 1, (int)floorf(c_hi + 1e-4f));
    int rmin = max(0,         (int)ceilf (r_lo - 1e-4f));
    int rmax = min(S_IMG - 1, (int)floorf(r_hi + 1e-4f));
    if (cmin > cmax || rmin > rmax) return;

    float4 e = make_float4(x, y, cz, __int_as_float(i));
    for (int rr = rmin; rr <= rmax; rr++) {
        for (int cc = cmin; cc <= cmax; cc++) {
            int pix = (b * S_IMG + rr) * S_IMG + cc;
            int slot = atomicAdd(&g_cnt[pix], 1);
            if (slot < CAP) g_list[slot * NPIX + pix] = e;
        }
    }
}

// -------- distance test + register bubble-insert (fully unrolled) ----------
__device__ __forceinline__ void try_insert(
    float4 q, float pxc, float pyc,
    unsigned long long* hk, float* hd)
{
    float ddx = pxc - q.x;
    float ddy = pyc - q.y;
    float d2  = fmaf(ddx, ddx, ddy * ddy);
    if (d2 < RAD2) {
        unsigned long long nk =
            ((unsigned long long)__float_as_uint(q.z) << 32)
            | (unsigned int)__float_as_int(q.w);
        float nd = d2;
        #pragma unroll
        for (int k = 0; k < KHITS; k++) {
            bool sw = nk < hk[k];
            unsigned long long tk = hk[k];
            float td = hd[k];
            hk[k] = sw ? nk : tk;  hd[k] = sw ? nd : td;
            nk    = sw ? tk : nk;  nd    = sw ? td : nd;
        }
    }
}

// ----------------------------------------------------------------- render --
__global__ __launch_bounds__(256) void render_px_kernel(
    const float* __restrict__ colors,   // [B, N, 3]
    float* __restrict__ out)            // [B, S, S, 3]
{
    const int pix = blockIdx.x * blockDim.x + threadIdx.x;  // 0 .. B*S*S-1
    const int b   = pix >> 14;                              // / (S*S)

    const float inv = 1.0f / (float)S_IMG;
    const int col = pix & (S_IMG - 1);
    const int row = (pix >> 7) & (S_IMG - 1);
    const float pxc = 1.0f - (2.0f * col + 1.0f) * inv;
    const float pyc = 1.0f - (2.0f * row + 1.0f) * inv;

    // register-resident sorted top-16 (ascending by key)
    // invalid slot: key = KEY_MAX, d2 = RAD2 (alpha == 0)
    unsigned long long hk[KHITS];
    float hd[KHITS];
    #pragma unroll
    for (int k = 0; k < KHITS; k++) { hk[k] = KEY_MAX; hd[k] = RAD2; }

    // PDL: preamble above overlaps K1; wait for K1 completion (no early
    // trigger in K1 -> all its writes are visible after this returns).
    cudaGridDependencySynchronize();

    const int cnt = min(g_cnt[pix], CAP);
    g_cnt[pix] = 0;                     // restore zero state for next call

    // ---- candidate loop: 4-wide batched loads (MLP = 4) ----
    int j = 0;
    for (; j + 4 <= cnt; j += 4) {
        float4 q0 = __ldg(&g_list[(j + 0) * NPIX + pix]);
        float4 q1 = __ldg(&g_list[(j + 1) * NPIX + pix]);
        float4 q2 = __ldg(&g_list[(j + 2) * NPIX + pix]);
        float4 q3 = __ldg(&g_list[(j + 3) * NPIX + pix]);
        try_insert(q0, pxc, pyc, hk, hd);
        try_insert(q1, pxc, pyc, hk, hd);
        try_insert(q2, pxc, pyc, hk, hd);
        try_insert(q3, pxc, pyc, hk, hd);
    }
    for (; j < cnt; j++) {
        float4 q = __ldg(&g_list[j * NPIX + pix]);
        try_insert(q, pxc, pyc, hk, hd);
    }

    // ---- front-to-back composite over already-sorted slots ----
    float T = 1.0f, r = 0.0f, g = 0.0f, bl = 0.0f;
    #pragma unroll
    for (int k = 0; k < KHITS; k++) {
        float a = 1.0f - hd[k] * INV_RAD2;     // == 0 for invalid slots
        a = fminf(fmaxf(a, 0.0f), 1.0f);
        float w = a * T;
        if (hk[k] != KEY_MAX) {
            const float* c = colors +
                (size_t)(b * NPTS +
                         (int)(unsigned int)(hk[k] & 0xffffffffu)) * 3;
            r  += w * __ldg(&c[0]);
            g  += w * __ldg(&c[1]);
            bl += w * __ldg(&c[2]);
        }
        T *= (1.0f - a);
    }

    float* o = out + (size_t)pix * 3;
    o[0] = r; o[1] = g; o[2] = bl;
}

// ----------------------------------------------------------------- launch ---
extern "C" void kernel_launch(void* const* d_in, const int* in_sizes, int n_in,
                              void* d_out, int out_size) {
    const float* points = (const float*)d_in[0];
    const float* eye    = (const float*)d_in[1];
    const float* colors = (const float*)d_in[2];
    float* out          = (float*)d_out;

    const int B = in_sizes[1] / 3;     // eye is [B,3]

    project_bin_kernel<<<(B * NPTS) / 256, 256>>>(points, eye);

    // PDL launch: render may begin (launch + preamble) while project runs;
    // cudaGridDependencySynchronize() inside gates the data-dependent part.
    cudaLaunchConfig_t cfg = {};
    cfg.gridDim  = dim3((B * S_IMG * S_IMG) / 256, 1, 1);
    cfg.blockDim = dim3(256, 1, 1);
    cfg.dynamicSmemBytes = 0;
    cfg.stream = 0;                      // legacy default stream (captured)
    cudaLaunchAttribute attr[1];
    attr[0].id = cudaLaunchAttributeProgrammaticStreamSerialization;
    attr[0].val.programmaticStreamSerializationAllowed = 1;
    cfg.attrs = attr;
    cfg.numAttrs = 1;
    cudaLaunchKernelEx(&cfg, render_px_kernel, colors, out);
}

// round 17
// speedup vs baseline: 1.2218x; 1.1420x over previous
#include <cuda_runtime.h>
#include <cuda_bf16.h>

// Renderer: B=2, N=2048 points, S=128 image, K=16 per pixel, alpha composite.
//
// EXACT-HIT per-pixel binning, 8-byte packed entries, register top-16, PDL:
//   K1 (project+bin): project each point; for each of the <=3x3 pixels whose
//       center might be in range, run the EXACT d2 < R^2 test (same fmaf
//       expression K2 used before -> identical hit set) and push a single
//       64-bit word  key = (z_bits<<32) | (d2q<<11) | idx  into that pixel's
//       list (d2q = round(d2/R^2 * 2^20), alpha error <= 5e-7).
//       Lists stored TRANSPOSED (list[slot][pixel]) -> coalesced 8B loads.
//   K2 (render, PDL): one thread per pixel; preamble + slot init overlap K1
//       via cudaGridDependencySynchronize(). Then: load hits 4-wide batched,
//       maintain a 16-slot register array sorted ascending by the packed key
//       (one u64 swap per slot, fully unrolled -> no local memory), and run
//       a BRANCHLESS front-to-back composite: empty slots decode to alpha=0
//       (clamped) and a valid dummy idx, contributing exactly 0.
//       Each thread re-zeroes its own counter (state returns to zero every
//       call -> graph-replay deterministic).
// Key order (z, d2, idx) == reference (z, idx) except on exact z-bit ties
// between distinct points (measure zero); deterministic under atomic order.

#define S_IMG    128
#define NPTS     2048
#define KHITS    16
#define RADIUS   0.02f
#define RAD2     (RADIUS * RADIUS)
#define ZNEAR    1.0f
#define FOCAL    1.7320508075688772f   // 1 / tan(30 deg)
#define B_MAX    2
#define NPIX     (B_MAX * S_IMG * S_IMG)   // 32768
#define CAP      32                    // actual hits/pixel: avg ~4.6, max ~15
#define KEY_MAX  0xffffffffffffffffULL
#define Q_SCALE  (1048576.0f / RAD2)   // d2 -> 2^20 * d2/R^2
#define A_SCALE  (1.0f / 1048576.0f)

__device__ int                g_cnt [NPIX];        // zero at steady state
__device__ unsigned long long g_list[CAP * NPIX];  // transposed, 8MB

// ------------------------------------------------------------ project+bin --
__global__ __launch_bounds__(256) void project_bin_kernel(
    const float* __restrict__ points,   // [B, N, 3]
    const float* __restrict__ eye)      // [B, 3]
{
    const int g = blockIdx.x * blockDim.x + threadIdx.x;
    const int b = g / NPTS;
    const int i = g - b * NPTS;

    const float ex = eye[b * 3 + 0];
    const float ey = eye[b * 3 + 1];
    const float ez = eye[b * 3 + 2];

    // camera basis (look-at origin, up = +y)
    float zn  = rsqrtf(ex * ex + ey * ey + ez * ez);
    float zax = -ex * zn, zay = -ey * zn, zaz = -ez * zn;
    float xax = zaz, xaz = -zax;                 // up x z (x.y == 0)
    float xn  = rsqrtf(xax * xax + xaz * xaz);
    xax *= xn; xaz *= xn;
    float yax = zay * xaz;
    float yay = zaz * xax - zax * xaz;
    float yaz = -zay * xax;

    const float* p = points + (size_t)g * 3;
    float dx = p[0] - ex, dy = p[1] - ey, dz = p[2] - ez;
    float cz = dx * zax + dy * zay + dz * zaz;
    if (cz <= ZNEAR) return;

    float cx = dx * xax + dz * xaz;
    float cy = dx * yax + dy * yay + dz * yaz;
    float s  = FOCAL / cz;
    float x  = cx * s;
    float y  = cy * s;

    // candidate pixel box (epsilon-widened; exact d2 test below)
    float c_lo = (1.0f - x - RADIUS) * (S_IMG * 0.5f) - 0.5f;
    float c_hi = (1.0f - x + RADIUS) * (S_IMG * 0.5f) - 0.5f;
    float r_lo = (1.0f - y - RADIUS) * (S_IMG * 0.5f) - 0.5f;
    float r_hi = (1.0f - y + RADIUS) * (S_IMG * 0.5f) - 0.5f;

    int cmin = max(0,         (int)ceilf (c_lo - 1e-4f));
    int cmax = min(S_IMG - 1, (int)floorf(c_hi + 1e-4f));
    int rmin = max(0,         (int)ceilf (r_lo - 1e-4f));
    int rmax = min(S_IMG - 1, (int)floorf(r_hi + 1e-4f));
    if (cmin > cmax || rmin > rmax) return;

    const float inv = 1.0f / (float)S_IMG;
    const unsigned long long zhi =
        ((unsigned long long)__float_as_uint(cz) << 32);

    for (int rr = rmin; rr <= rmax; rr++) {
        float pyc = 1.0f - (2.0f * rr + 1.0f) * inv;
        float ddy = pyc - y;
        for (int cc = cmin; cc <= cmax; cc++) {
            float pxc = 1.0f - (2.0f * cc + 1.0f) * inv;
            float ddx = pxc - x;
            float d2  = fmaf(ddx, ddx, ddy * ddy);   // EXACT hit test
            if (d2 < RAD2) {
                unsigned int q = (unsigned int)(d2 * Q_SCALE + 0.5f);
                q = min(q, 0x1FFFFFu);               // 21 bits
                unsigned long long key = zhi
                    | ((unsigned long long)q << 11)
                    | (unsigned int)i;               // 11 bits
                int pix = (b * S_IMG + rr) * S_IMG + cc;
                int slot = atomicAdd(&g_cnt[pix], 1);
                if (slot < CAP) g_list[slot * NPIX + pix] = key;
            }
        }
    }
}

// -------- single-u64 register bubble-insert (fully unrolled) ---------------
__device__ __forceinline__ void insert_key(unsigned long long nk,
                                           unsigned long long* hk)
{
    #pragma unroll
    for (int k = 0; k < KHITS; k++) {
        bool sw = nk < hk[k];
        unsigned long long tk = hk[k];
        hk[k] = sw ? nk : tk;
        nk    = sw ? tk : nk;
    }
}

// ----------------------------------------------------------------- render --
__global__ __launch_bounds__(256) void render_px_kernel(
    const float* __restrict__ colors,   // [B, N, 3]
    float* __restrict__ out)            // [B, S, S, 3]
{
    const int pix = blockIdx.x * blockDim.x + threadIdx.x;  // 0 .. B*S*S-1
    const int b   = pix >> 14;                              // / (S*S)

    // register-resident sorted top-16 (ascending by key).
    // KEY_MAX decodes to q=0x1FFFFF -> alpha clamps to 0, idx=2047 (valid).
    unsigned long long hk[KHITS];
    #pragma unroll
    for (int k = 0; k < KHITS; k++) hk[k] = KEY_MAX;

    // PDL: preamble above overlaps K1; wait for K1 completion.
    cudaGridDependencySynchronize();

    const int cnt = min(g_cnt[pix], CAP);
    g_cnt[pix] = 0;                     // restore zero state for next call

    // ---- hit loop: 4-wide batched 8B loads (MLP = 4), no distance test ----
    int j = 0;
    for (; j + 4 <= cnt; j += 4) {
        unsigned long long k0 = __ldg(&g_list[(j + 0) * NPIX + pix]);
        unsigned long long k1 = __ldg(&g_list[(j + 1) * NPIX + pix]);
        unsigned long long k2 = __ldg(&g_list[(j + 2) * NPIX + pix]);
        unsigned long long k3 = __ldg(&g_list[(j + 3) * NPIX + pix]);
        insert_key(k0, hk);
        insert_key(k1, hk);
        insert_key(k2, hk);
        insert_key(k3, hk);
    }
    for (; j < cnt; j++) {
        insert_key(__ldg(&g_list[j * NPIX + pix]), hk);
    }

    // ---- branchless front-to-back composite over sorted slots ----
    float T = 1.0f, r = 0.0f, g = 0.0f, bl = 0.0f;
    #pragma unroll
    for (int k = 0; k < KHITS; k++) {
        unsigned int v   = (unsigned int)hk[k];
        unsigned int q   = v >> 11;
        unsigned int idx = v & 0x7FFu;
        float a = 1.0f - (float)q * A_SCALE;   // <= 0 for empty slots
        a = fminf(fmaxf(a, 0.0f), 1.0f);
        float w = a * T;
        const float* c = colors + (size_t)(b * NPTS + idx) * 3;
        r  += w * __ldg(&c[0]);
        g  += w * __ldg(&c[1]);
        bl += w * __ldg(&c[2]);
        T *= (1.0f - a);
    }

    float* o = out + (size_t)pix * 3;
    o[0] = r; o[1] = g; o[2] = bl;
}

// ----------------------------------------------------------------- launch ---
extern "C" void kernel_launch(void* const* d_in, const int* in_sizes, int n_in,
                              void* d_out, int out_size) {
    const float* points = (const float*)d_in[0];
    const float* eye    = (const float*)d_in[1];
    const float* colors = (const float*)d_in[2];
    float* out          = (float*)d_out;

    const int B = in_sizes[1] / 3;     // eye is [B,3]

    project_bin_kernel<<<(B * NPTS) / 256, 256>>>(points, eye);

    // PDL launch: render may begin (launch + preamble) while project runs;
    // cudaGridDependencySynchronize() inside gates the data-dependent part.
    cudaLaunchConfig_t cfg = {};
    cfg.gridDim  = dim3((B * S_IMG * S_IMG) / 256, 1, 1);
    cfg.blockDim = dim3(256, 1, 1);
    cfg.dynamicSmemBytes = 0;
    cfg.stream = 0;                      // legacy default stream (captured)
    cudaLaunchAttribute attr[1];
    attr[0].id = cudaLaunchAttributeProgrammaticStreamSerialization;
    attr[0].val.programmaticStreamSerializationAllowed = 1;
    cfg.attrs = attr;
    cfg.numAttrs = 1;
    cudaLaunchKernelEx(&cfg, render_px_kernel, colors, out);
}